// round 10
// baseline (speedup 1.0000x reference)
#include <cuda_runtime.h>
#include <cuda_fp16.h>
#include <cstdint>

// ---------------------------------------------------------------------------
//   x: (2,1024,32,512) fp32 -> M=65536, K=512
//   qkv = x @ [w_q|w_kv] -> N=1536 ; attention per (b,s,h): n=32, d=64
//   out = att @ w_out -> (65536, 512) fp32
// ---------------------------------------------------------------------------

#define NELEM_QKV 33554432

__device__ __half g_xh[(size_t)65536 * 512];   // x converted to fp16
__device__ __half g_wqkvT[1536 * 512];         // [n][k] K-major
__device__ __half g_woutT[512 * 512];          // [n][k] K-major
__device__ __half g_q[NELEM_QKV];
__device__ __half g_k[NELEM_QKV];
__device__ __half g_v[NELEM_QKV];
__device__ __half g_att[(size_t)65536 * 512];
__device__ float  g_cos[1024];                 // [pos][freq]
__device__ float  g_sin[1024];
__device__ int    g_mask[2];

__device__ __forceinline__ unsigned pack_h2(float a, float b) {
    __half2 h = __floats2half2_rn(a, b);
    return *reinterpret_cast<unsigned*>(&h);
}
__device__ __forceinline__ uint32_t smem_u32(const void* p) {
    uint32_t r;
    asm("{ .reg .u64 t; cvta.to.shared.u64 t, %1; cvt.u32.u64 %0, t; }"
        : "=r"(r) : "l"(p));
    return r;
}
__device__ __forceinline__ void cp16(uint32_t d, const void* s) {
    asm volatile("cp.async.cg.shared.global [%0], [%1], 16;" :: "r"(d), "l"(s) : "memory");
}
#define CP_COMMIT() asm volatile("cp.async.commit_group;" ::: "memory")

#define MMA_16816(D, A, B0, B1)                                               \
    asm volatile(                                                             \
        "mma.sync.aligned.m16n8k16.row.col.f32.f16.f16.f32 "                  \
        "{%0,%1,%2,%3},{%4,%5,%6,%7},{%8,%9},{%0,%1,%2,%3};"                  \
        : "+f"(D[0]), "+f"(D[1]), "+f"(D[2]), "+f"(D[3])                      \
        : "r"(A[0]), "r"(A[1]), "r"(A[2]), "r"(A[3]), "r"(B0), "r"(B1))

#define LDSM4(R, addr)                                                        \
    asm volatile("ldmatrix.sync.aligned.m8n8.x4.shared.b16 {%0,%1,%2,%3}, [%4];" \
        : "=r"((R)[0]), "=r"((R)[1]), "=r"((R)[2]), "=r"((R)[3]) : "r"(addr))

// ---------------------------------------------------------------------------
// Prep: x -> fp16, weights transposed to [n][k] fp16, rope tables, mask.
// ---------------------------------------------------------------------------
__global__ void prep_kernel(const float* __restrict__ wq,
                            const float* __restrict__ wkv,
                            const float* __restrict__ wout,
                            const float* __restrict__ invf,
                            const unsigned char* __restrict__ maskp,
                            const float* __restrict__ x)
{
    int i = blockIdx.x * blockDim.x + threadIdx.x;
    int stride = gridDim.x * blockDim.x;

    for (size_t idx = i; idx < (size_t)65536 * 512 / 4; idx += stride) {
        float4 v = reinterpret_cast<const float4*>(x)[idx];
        uint2 st;
        st.x = pack_h2(v.x, v.y);
        st.y = pack_h2(v.z, v.w);
        *reinterpret_cast<uint2*>(&g_xh[idx * 4]) = st;
    }
    for (int idx = i; idx < 1536 * 512; idx += stride) {
        int n = idx >> 9, k = idx & 511;
        float v = (n < 512) ? wq[k * 512 + n] : wkv[k * 1024 + (n - 512)];
        g_wqkvT[idx] = __float2half_rn(v);
    }
    for (int idx = i; idx < 512 * 512; idx += stride) {
        int n = idx >> 9, k = idx & 511;
        g_woutT[idx] = __float2half_rn(wout[k * 512 + n]);
    }
    for (int idx = i; idx < 1024; idx += stride) {
        int pos = idx >> 5, f = idx & 31;
        float a = (float)pos * invf[f];
        g_cos[idx] = cosf(a);
        g_sin[idx] = sinf(a);
    }
    if (i == 0) {
        unsigned char c0 = maskp[0], c1 = maskp[1], c2 = maskp[2], c3 = maskp[3];
        int m0, m1;
        if (c1 | c2 | c3) { m0 = (c0 != 0); m1 = (c1 != 0); }
        else {
            int i1 = ((const int*)maskp)[1];
            if (i1 == 0 || i1 == 1) { m0 = (c0 != 0); m1 = i1; }
            else                    { m0 = (c0 != 0); m1 = (c1 != 0); }
        }
        g_mask[0] = m0; g_mask[1] = m1;
    }
}

// ---------------------------------------------------------------------------
// HGEMM: C(128x128 per CTA) = A[m][k] * B[n][k]^T, fp16 in, fp32 accum.
// 4 warps, warp tile 64x64 (8 LDSM.x4 per 32 HMMA), BK=64,
// 3-stage cp.async ring (32KB/stage), 128B-XOR swizzled smem.
// MODE 0: A=g_xh, B=g_wqkvT -> RoPE/scale epilogue, scatter q/k/v.
// MODE 1: A=g_att, B=g_woutT -> fp32 store to d_out.
// ---------------------------------------------------------------------------
template <int MODE>
__global__ __launch_bounds__(128, 2) void hgemm(float* __restrict__ Cout)
{
    const __half* __restrict__ AG = (MODE == 0) ? g_xh : g_att;
    const __half* __restrict__ BG = (MODE == 0) ? g_wqkvT : g_woutT;

    extern __shared__ char smem[];                 // 3 * 32768
    const uint32_t sbase = smem_u32(smem);

    const int tid = threadIdx.x, lane = tid & 31, warp = tid >> 5;
    const int warpM = warp & 1, warpN = warp >> 1;       // 2 x 2 warps
    const int g = lane >> 2, c2 = (lane & 3) * 2;
    const int bm0 = blockIdx.y * 128, bn0 = blockIdx.x * 128;

    // cp.async stage loader: A rows 0..127 (m), B rows 0..127 (n), 64 halves each
    const int lr = tid >> 3, lc = tid & 7;         // 16 rows/pass, 8 chunks/row
    auto load_stage = [&](int kb, uint32_t buf) {
#pragma unroll
        for (int j = 0; j < 8; j++) {
            int r = lr + j * 16;
            uint32_t d = buf + r * 128 + ((lc * 16) ^ ((r & 7) << 4));
            cp16(d, AG + (size_t)(bm0 + r) * 512 + kb + lc * 8);
            cp16(d + 16384, BG + (size_t)(bn0 + r) * 512 + kb + lc * 8);
        }
    };

    float acc[4][8][4];
#pragma unroll
    for (int a = 0; a < 4; a++)
#pragma unroll
        for (int b = 0; b < 8; b++)
#pragma unroll
            for (int c = 0; c < 4; c++) acc[a][b][c] = 0.f;

    load_stage(0, sbase);            CP_COMMIT();
    load_stage(64, sbase + 32768);   CP_COMMIT();
    load_stage(128, sbase + 65536);  CP_COMMIT();

    // ldmatrix per-lane address pieces (swizzle sel depends only on lane&7)
    const uint32_t sel = (lane & 7) << 4;
    const uint32_t klane = (lane >> 4) * 16;                       // bytes
    const uint32_t arow = (uint32_t)(warpM * 64 + (lane & 15)) * 128;
    const uint32_t brow = (uint32_t)(warpN * 64 + (lane & 15)) * 128;

    for (int ks = 0; ks < 8; ks++) {
        asm volatile("cp.async.wait_group 2;" ::: "memory");
        __syncthreads();
        const uint32_t bufA = sbase + (ks % 3) * 32768;
        const uint32_t bufB = bufA + 16384;

#pragma unroll
        for (int kk = 0; kk < 4; kk++) {
            const uint32_t kc = (klane + kk * 32) ^ sel;
            unsigned afr[4][4];
#pragma unroll
            for (int mt = 0; mt < 4; mt++)
                LDSM4(afr[mt], bufA + arow + mt * 2048 + kc);
            unsigned braw[4][4];
#pragma unroll
            for (int nt2 = 0; nt2 < 4; nt2++)
                LDSM4(braw[nt2], bufB + brow + nt2 * 2048 + kc);
#pragma unroll
            for (int mt = 0; mt < 4; mt++)
#pragma unroll
                for (int nt2 = 0; nt2 < 4; nt2++) {
                    MMA_16816(acc[mt][2 * nt2 + 0], afr[mt], braw[nt2][0], braw[nt2][2]);
                    MMA_16816(acc[mt][2 * nt2 + 1], afr[mt], braw[nt2][1], braw[nt2][3]);
                }
        }
        __syncthreads();
        if (ks + 3 < 8) load_stage((ks + 3) * 64, sbase + (ks % 3) * 32768);
        CP_COMMIT();                      // empty group when nothing loaded
    }

    // ---- epilogue ----
#pragma unroll
    for (int mt = 0; mt < 4; mt++) {
#pragma unroll
        for (int nt = 0; nt < 8; nt++) {
            const int col = bn0 + warpN * 64 + nt * 8 + c2;
#pragma unroll
            for (int hf = 0; hf < 2; hf++) {
                const int r = bm0 + warpM * 64 + mt * 16 + g + hf * 8;
                float v0 = acc[mt][nt][hf * 2 + 0];
                float v1 = acc[mt][nt][hf * 2 + 1];
                if (MODE == 1) {
                    float2 st; st.x = v0; st.y = v1;
                    *reinterpret_cast<float2*>(&Cout[(size_t)r * 512 + col]) = st;
                } else {
                    const int sec = col >> 9;       // 0=q, 1=k, 2=v
                    const int jh = col & 511;
                    const int h = jh >> 6, d = jh & 63, f = d >> 1;
                    const int pos = r & 31, bs = r >> 5;
                    if (sec == 0) { v0 *= 0.125f; v1 *= 0.125f; }
                    if (sec < 2) {
                        float cs = g_cos[pos * 32 + f], sn = g_sin[pos * 32 + f];
                        float o0 = v0 * cs - v1 * sn;
                        float o1 = v1 * cs + v0 * sn;
                        v0 = o0; v1 = o1;
                    }
                    __half2 hv = __floats2half2_rn(v0, v1);
                    size_t dst = ((size_t)((bs * 8 + h) * 32 + pos)) * 64 + d;
                    if (sec == 0)      *reinterpret_cast<__half2*>(&g_q[dst]) = hv;
                    else if (sec == 1) *reinterpret_cast<__half2*>(&g_k[dst]) = hv;
                    else               *reinterpret_cast<__half2*>(&g_v[dst]) = hv;
                }
            }
        }
    }
}

// ---------------------------------------------------------------------------
// Attention: one warp per (b*s, head). mma.sync, register softmax.
// ---------------------------------------------------------------------------
__global__ __launch_bounds__(64) void attn_kernel(const float* __restrict__ pos_bias)
{
    __shared__ __half sh[2][7168];
    const int lane = threadIdx.x & 31, w = threadIdx.x >> 5;
    const int hh = blockIdx.x * 2 + w;
    const int bs = hh >> 3, h = hh & 7, b = bs >> 10;
    const int g = lane >> 2, c2 = (lane & 3) * 2;

    const __half* qg = g_q + (size_t)hh * 2048;
    const __half* kg = g_k + (size_t)hh * 2048;
    const __half* vg = g_v + (size_t)hh * 2048;
    __half* Qs = sh[w];
    __half* Ks = sh[w] + 2304;
    __half* Vt = sh[w] + 4608;

    if (g_mask[b]) {
#pragma unroll
        for (int it = 0; it < 16; it++) {
            int i = it * 32 + lane;
            int tok = i >> 4, p4 = (i & 15) * 4;
            uint2 v = *reinterpret_cast<const uint2*>(&vg[tok * 64 + p4]);
            *reinterpret_cast<uint2*>(
                &g_att[((size_t)(bs * 32 + tok)) * 512 + h * 64 + p4]) = v;
        }
        return;
    }

#pragma unroll
    for (int it = 0; it < 16; it++) {
        int i = it * 32 + lane;
        int tok = i >> 4, p4 = (i & 15) * 4;
        uint2 qv = *reinterpret_cast<const uint2*>(&qg[tok * 64 + p4]);
        *reinterpret_cast<uint2*>(&Qs[tok * 72 + p4]) = qv;
        uint2 kv = *reinterpret_cast<const uint2*>(&kg[tok * 64 + p4]);
        *reinterpret_cast<uint2*>(&Ks[tok * 72 + p4]) = kv;
        uint2 vv = *reinterpret_cast<const uint2*>(&vg[tok * 64 + p4]);
        __half hbuf[4];
        *reinterpret_cast<uint2*>(hbuf) = vv;
#pragma unroll
        for (int q = 0; q < 4; q++) Vt[(p4 + q) * 40 + tok] = hbuf[q];
    }
    __syncwarp();

    float sacc[2][4][4];
#pragma unroll
    for (int a = 0; a < 2; a++)
#pragma unroll
        for (int n = 0; n < 4; n++)
#pragma unroll
            for (int e = 0; e < 4; e++) sacc[a][n][e] = 0.f;

#pragma unroll
    for (int kt = 0; kt < 4; kt++) {
        const int k0 = kt * 16;
        unsigned aq[2][4];
#pragma unroll
        for (int mt = 0; mt < 2; mt++) {
            int m0 = mt * 16;
            aq[mt][0] = *reinterpret_cast<unsigned*>(&Qs[(m0 + g) * 72 + k0 + c2]);
            aq[mt][1] = *reinterpret_cast<unsigned*>(&Qs[(m0 + g + 8) * 72 + k0 + c2]);
            aq[mt][2] = *reinterpret_cast<unsigned*>(&Qs[(m0 + g) * 72 + k0 + c2 + 8]);
            aq[mt][3] = *reinterpret_cast<unsigned*>(&Qs[(m0 + g + 8) * 72 + k0 + c2 + 8]);
        }
        unsigned bk[4][2];
#pragma unroll
        for (int nt = 0; nt < 4; nt++) {
            int n = nt * 8 + g;
            bk[nt][0] = *reinterpret_cast<unsigned*>(&Ks[n * 72 + k0 + c2]);
            bk[nt][1] = *reinterpret_cast<unsigned*>(&Ks[n * 72 + k0 + c2 + 8]);
        }
#pragma unroll
        for (int mt = 0; mt < 2; mt++)
#pragma unroll
            for (int nt = 0; nt < 4; nt++)
                MMA_16816(sacc[mt][nt], aq[mt], bk[nt][0], bk[nt][1]);
    }

    const float* pb = pos_bias + h * 1024;
#pragma unroll
    for (int mt = 0; mt < 2; mt++)
#pragma unroll
        for (int nt = 0; nt < 4; nt++)
#pragma unroll
            for (int hf = 0; hf < 2; hf++) {
                int r = mt * 16 + g + hf * 8;
                int col = nt * 8 + c2;
                sacc[mt][nt][hf * 2 + 0] += pb[r * 32 + col];
                sacc[mt][nt][hf * 2 + 1] += pb[r * 32 + col + 1];
            }

#pragma unroll
    for (int mt = 0; mt < 2; mt++)
#pragma unroll
        for (int hf = 0; hf < 2; hf++) {
            float mx = -1e30f;
#pragma unroll
            for (int nt = 0; nt < 4; nt++) {
                mx = fmaxf(mx, sacc[mt][nt][hf * 2 + 0]);
                mx = fmaxf(mx, sacc[mt][nt][hf * 2 + 1]);
            }
            mx = fmaxf(mx, __shfl_xor_sync(0xffffffffu, mx, 1));
            mx = fmaxf(mx, __shfl_xor_sync(0xffffffffu, mx, 2));
            float sum = 0.f;
#pragma unroll
            for (int nt = 0; nt < 4; nt++) {
#pragma unroll
                for (int j = 0; j < 2; j++) {
                    float e = __expf(sacc[mt][nt][hf * 2 + j] - mx);
                    sacc[mt][nt][hf * 2 + j] = e;
                    sum += e;
                }
            }
            sum += __shfl_xor_sync(0xffffffffu, sum, 1);
            sum += __shfl_xor_sync(0xffffffffu, sum, 2);
            float inv = 1.f / sum;
#pragma unroll
            for (int nt = 0; nt < 4; nt++) {
                sacc[mt][nt][hf * 2 + 0] *= inv;
                sacc[mt][nt][hf * 2 + 1] *= inv;
            }
        }

    unsigned pa[2][2][4];
#pragma unroll
    for (int mt = 0; mt < 2; mt++)
#pragma unroll
        for (int kt = 0; kt < 2; kt++) {
            pa[mt][kt][0] = pack_h2(sacc[mt][2 * kt][0], sacc[mt][2 * kt][1]);
            pa[mt][kt][1] = pack_h2(sacc[mt][2 * kt][2], sacc[mt][2 * kt][3]);
            pa[mt][kt][2] = pack_h2(sacc[mt][2 * kt + 1][0], sacc[mt][2 * kt + 1][1]);
            pa[mt][kt][3] = pack_h2(sacc[mt][2 * kt + 1][2], sacc[mt][2 * kt + 1][3]);
        }

    float oacc[2][8][4];
#pragma unroll
    for (int a = 0; a < 2; a++)
#pragma unroll
        for (int d = 0; d < 8; d++)
#pragma unroll
            for (int e = 0; e < 4; e++) oacc[a][d][e] = 0.f;

#pragma unroll
    for (int dt = 0; dt < 8; dt++) {
        unsigned bv[2][2];
#pragma unroll
        for (int kt = 0; kt < 2; kt++) {
            bv[kt][0] = *reinterpret_cast<unsigned*>(&Vt[(dt * 8 + g) * 40 + kt * 16 + c2]);
            bv[kt][1] = *reinterpret_cast<unsigned*>(&Vt[(dt * 8 + g) * 40 + kt * 16 + c2 + 8]);
        }
#pragma unroll
        for (int mt = 0; mt < 2; mt++)
#pragma unroll
            for (int kt = 0; kt < 2; kt++)
                MMA_16816(oacc[mt][dt], pa[mt][kt], bv[kt][0], bv[kt][1]);
    }

#pragma unroll
    for (int mt = 0; mt < 2; mt++)
#pragma unroll
        for (int dt = 0; dt < 8; dt++)
#pragma unroll
            for (int hf = 0; hf < 2; hf++) {
                int r = mt * 16 + g + hf * 8;
                int d = dt * 8 + c2;
                __half2 hv = __floats2half2_rn(oacc[mt][dt][hf * 2 + 0],
                                               oacc[mt][dt][hf * 2 + 1]);
                *reinterpret_cast<__half2*>(
                    &g_att[((size_t)(bs * 32 + r)) * 512 + h * 64 + d]) = hv;
            }
}

// ---------------------------------------------------------------------------
extern "C" void kernel_launch(void* const* d_in, const int* in_sizes, int n_in,
                              void* d_out, int out_size)
{
    const float *x = 0, *pos_bias = 0, *wq = 0, *wkv = 0, *wout = 0, *invf = 0;
    const unsigned char* maskp = 0;
    for (int i = 0; i < n_in; i++) {
        int s = in_sizes[i];
        if (s == 33554432)      x = (const float*)d_in[i];
        else if (s == 8192)     pos_bias = (const float*)d_in[i];
        else if (s == 2)        maskp = (const unsigned char*)d_in[i];
        else if (s == 524288)   wkv = (const float*)d_in[i];
        else if (s == 32)       invf = (const float*)d_in[i];
        else if (s == 262144) { if (!wq) wq = (const float*)d_in[i];
                                else     wout = (const float*)d_in[i]; }
    }
    float* out = (float*)d_out;

    const int SMEM = 3 * 32768;
    cudaFuncSetAttribute(hgemm<0>, cudaFuncAttributeMaxDynamicSharedMemorySize, SMEM);
    cudaFuncSetAttribute(hgemm<1>, cudaFuncAttributeMaxDynamicSharedMemorySize, SMEM);

    prep_kernel<<<2048, 256>>>(wq, wkv, wout, invf, maskp, x);
    hgemm<0><<<dim3(12, 512), 128, SMEM>>>(nullptr);   // QKV + RoPE
    attn_kernel<<<8192, 64>>>(pos_bias);               // per-head attention
    hgemm<1><<<dim3(4, 512), 128, SMEM>>>(out);        // out projection
}

// round 12
// speedup vs baseline: 1.4831x; 1.4831x over previous
#include <cuda_runtime.h>
#include <cuda_fp16.h>
#include <cstdint>

// ---------------------------------------------------------------------------
//   x: (2,1024,32,512) fp32 -> M=65536, K=512
//   qkv = x @ [w_q|w_kv] -> N=1536 ; attention per (b,s,h): n=32, d=64
//   out = att @ w_out -> (65536, 512) fp32
// ---------------------------------------------------------------------------

#define NELEM_QKV 33554432

__device__ __half g_xh[(size_t)65536 * 512];   // x converted to fp16
__device__ __half g_wqkvT[1536 * 512];         // [n][k] K-major
__device__ __half g_woutT[512 * 512];          // [n][k] K-major
__device__ __half g_q[NELEM_QKV];
__device__ __half g_k[NELEM_QKV];
__device__ __half g_v[NELEM_QKV];
__device__ __half g_att[(size_t)65536 * 512];
__device__ float  g_cos[1024];                 // [pos][freq]
__device__ float  g_sin[1024];
__device__ int    g_mask[2];

__device__ __forceinline__ unsigned pack_h2(float a, float b) {
    __half2 h = __floats2half2_rn(a, b);
    return *reinterpret_cast<unsigned*>(&h);
}
__device__ __forceinline__ uint32_t smem_u32(const void* p) {
    uint32_t r;
    asm("{ .reg .u64 t; cvta.to.shared.u64 t, %1; cvt.u32.u64 %0, t; }"
        : "=r"(r) : "l"(p));
    return r;
}
__device__ __forceinline__ void cp16(uint32_t d, const void* s) {
    asm volatile("cp.async.cg.shared.global [%0], [%1], 16;" :: "r"(d), "l"(s) : "memory");
}
#define CP_COMMIT() asm volatile("cp.async.commit_group;" ::: "memory")

#define MMA_16816(D, A, B0, B1)                                               \
    asm volatile(                                                             \
        "mma.sync.aligned.m16n8k16.row.col.f32.f16.f16.f32 "                  \
        "{%0,%1,%2,%3},{%4,%5,%6,%7},{%8,%9},{%0,%1,%2,%3};"                  \
        : "+f"(D[0]), "+f"(D[1]), "+f"(D[2]), "+f"(D[3])                      \
        : "r"(A[0]), "r"(A[1]), "r"(A[2]), "r"(A[3]), "r"(B0), "r"(B1))

#define LDSM4(R, addr)                                                        \
    asm volatile("ldmatrix.sync.aligned.m8n8.x4.shared.b16 {%0,%1,%2,%3}, [%4];" \
        : "=r"((R)[0]), "=r"((R)[1]), "=r"((R)[2]), "=r"((R)[3]) : "r"(addr))

// ---------------------------------------------------------------------------
// Prep: x -> fp16, weights transposed to [n][k] fp16, rope tables, mask.
// ---------------------------------------------------------------------------
__global__ void prep_kernel(const float* __restrict__ wq,
                            const float* __restrict__ wkv,
                            const float* __restrict__ wout,
                            const float* __restrict__ invf,
                            const unsigned char* __restrict__ maskp,
                            const float* __restrict__ x)
{
    int i = blockIdx.x * blockDim.x + threadIdx.x;
    int stride = gridDim.x * blockDim.x;

    for (size_t idx = i; idx < (size_t)65536 * 512 / 4; idx += stride) {
        float4 v = reinterpret_cast<const float4*>(x)[idx];
        uint2 st;
        st.x = pack_h2(v.x, v.y);
        st.y = pack_h2(v.z, v.w);
        *reinterpret_cast<uint2*>(&g_xh[idx * 4]) = st;
    }
    for (int idx = i; idx < 1536 * 512; idx += stride) {
        int n = idx >> 9, k = idx & 511;
        float v = (n < 512) ? wq[k * 512 + n] : wkv[k * 1024 + (n - 512)];
        g_wqkvT[idx] = __float2half_rn(v);
    }
    for (int idx = i; idx < 512 * 512; idx += stride) {
        int n = idx >> 9, k = idx & 511;
        g_woutT[idx] = __float2half_rn(wout[k * 512 + n]);
    }
    for (int idx = i; idx < 1024; idx += stride) {
        int pos = idx >> 5, f = idx & 31;
        float a = (float)pos * invf[f];
        g_cos[idx] = cosf(a);
        g_sin[idx] = sinf(a);
    }
    if (i == 0) {
        unsigned char c0 = maskp[0], c1 = maskp[1], c2 = maskp[2], c3 = maskp[3];
        int m0, m1;
        if (c1 | c2 | c3) { m0 = (c0 != 0); m1 = (c1 != 0); }
        else {
            int i1 = ((const int*)maskp)[1];
            if (i1 == 0 || i1 == 1) { m0 = (c0 != 0); m1 = i1; }
            else                    { m0 = (c0 != 0); m1 = (c1 != 0); }
        }
        g_mask[0] = m0; g_mask[1] = m1;
    }
}

// ---------------------------------------------------------------------------
// HGEMM: C(128x128 per CTA) = A[m][k] * B[n][k]^T, fp16 in, fp32 accum.
// 4 warps, warp tile 64x64 (8 LDSM.x4 per 32 HMMA), BK=64,
// 3-stage cp.async ring (32KB/stage), 128B-XOR swizzled smem,
// DOUBLE-BUFFERED register fragments: kk+1 LDSMs issue before kk MMAs.
// MODE 0: A=g_xh, B=g_wqkvT -> RoPE/scale epilogue, scatter q/k/v.
// MODE 1: A=g_att, B=g_woutT -> fp32 store to d_out.
// ---------------------------------------------------------------------------
template <int MODE>
__global__ __launch_bounds__(128, 2) void hgemm(float* __restrict__ Cout)
{
    const __half* __restrict__ AG = (MODE == 0) ? g_xh : g_att;
    const __half* __restrict__ BG = (MODE == 0) ? g_wqkvT : g_woutT;

    extern __shared__ char smem[];                 // 3 * 32768
    const uint32_t sbase = smem_u32(smem);

    const int tid = threadIdx.x, lane = tid & 31, warp = tid >> 5;
    const int warpM = warp & 1, warpN = warp >> 1;       // 2 x 2 warps
    const int g = lane >> 2, c2 = (lane & 3) * 2;
    const int bm0 = blockIdx.y * 128, bn0 = blockIdx.x * 128;

    // cp.async stage loader: A rows 0..127 (m), B rows 0..127 (n), 64 halves each
    const int lr = tid >> 3, lc = tid & 7;         // 16 rows/pass, 8 chunks/row
    auto load_stage = [&](int kb, uint32_t buf) {
#pragma unroll
        for (int j = 0; j < 8; j++) {
            int r = lr + j * 16;
            uint32_t d = buf + r * 128 + ((lc * 16) ^ ((r & 7) << 4));
            cp16(d, AG + (size_t)(bm0 + r) * 512 + kb + lc * 8);
            cp16(d + 16384, BG + (size_t)(bn0 + r) * 512 + kb + lc * 8);
        }
    };

    float acc[4][8][4];
#pragma unroll
    for (int a = 0; a < 4; a++)
#pragma unroll
        for (int b = 0; b < 8; b++)
#pragma unroll
            for (int c = 0; c < 4; c++) acc[a][b][c] = 0.f;

    load_stage(0, sbase);            CP_COMMIT();
    load_stage(64, sbase + 32768);   CP_COMMIT();
    load_stage(128, sbase + 65536);  CP_COMMIT();

    // ldmatrix per-lane address pieces (swizzle sel depends only on lane&7)
    const uint32_t sel = (lane & 7) << 4;
    const uint32_t klane = (lane >> 4) * 16;                       // bytes
    const uint32_t arow = (uint32_t)(warpM * 64 + (lane & 15)) * 128;
    const uint32_t brow = (uint32_t)(warpN * 64 + (lane & 15)) * 128;

    unsigned afr[2][4][4];     // [buf][mt][4]
    unsigned bfr[2][4][4];     // [buf][nt][4]

    for (int ks = 0; ks < 8; ks++) {
        asm volatile("cp.async.wait_group 2;" ::: "memory");
        __syncthreads();
        const uint32_t bufA = sbase + (ks % 3) * 32768;
        const uint32_t bufB = bufA + 16384;

        // preload kk = 0 fragments into buffer 0
        {
            const uint32_t kc = klane ^ sel;
#pragma unroll
            for (int mt = 0; mt < 4; mt++)
                LDSM4(afr[0][mt], bufA + arow + mt * 2048 + kc);
#pragma unroll
            for (int nt = 0; nt < 4; nt++)
                LDSM4(bfr[0][nt], bufB + brow + nt * 2048 + kc);
        }

#pragma unroll
        for (int kk = 0; kk < 4; kk++) {
            const int cur = kk & 1, nxt = cur ^ 1;
            if (kk < 3) {       // issue kk+1 loads before kk MMAs
                const uint32_t kc = (klane + (kk + 1) * 32) ^ sel;
#pragma unroll
                for (int mt = 0; mt < 4; mt++)
                    LDSM4(afr[nxt][mt], bufA + arow + mt * 2048 + kc);
#pragma unroll
                for (int nt = 0; nt < 4; nt++)
                    LDSM4(bfr[nxt][nt], bufB + brow + nt * 2048 + kc);
            }
#pragma unroll
            for (int mt = 0; mt < 4; mt++)
#pragma unroll
                for (int nt = 0; nt < 4; nt++) {
                    MMA_16816(acc[mt][2 * nt + 0], afr[cur][mt], bfr[cur][nt][0], bfr[cur][nt][2]);
                    MMA_16816(acc[mt][2 * nt + 1], afr[cur][mt], bfr[cur][nt][1], bfr[cur][nt][3]);
                }
        }
        __syncthreads();
        if (ks + 3 < 8) load_stage((ks + 3) * 64, sbase + (ks % 3) * 32768);
        CP_COMMIT();                      // empty group when nothing loaded
    }

    // ---- epilogue ----
#pragma unroll
    for (int mt = 0; mt < 4; mt++) {
#pragma unroll
        for (int nt = 0; nt < 8; nt++) {
            const int col = bn0 + warpN * 64 + nt * 8 + c2;
#pragma unroll
            for (int hf = 0; hf < 2; hf++) {
                const int r = bm0 + warpM * 64 + mt * 16 + g + hf * 8;
                float v0 = acc[mt][nt][hf * 2 + 0];
                float v1 = acc[mt][nt][hf * 2 + 1];
                if (MODE == 1) {
                    float2 st; st.x = v0; st.y = v1;
                    *reinterpret_cast<float2*>(&Cout[(size_t)r * 512 + col]) = st;
                } else {
                    const int sec = col >> 9;       // 0=q, 1=k, 2=v
                    const int jh = col & 511;
                    const int h = jh >> 6, d = jh & 63, f = d >> 1;
                    const int pos = r & 31, bs = r >> 5;
                    if (sec == 0) { v0 *= 0.125f; v1 *= 0.125f; }
                    if (sec < 2) {
                        float cs = g_cos[pos * 32 + f], sn = g_sin[pos * 32 + f];
                        float o0 = v0 * cs - v1 * sn;
                        float o1 = v1 * cs + v0 * sn;
                        v0 = o0; v1 = o1;
                    }
                    __half2 hv = __floats2half2_rn(v0, v1);
                    size_t dst = ((size_t)((bs * 8 + h) * 32 + pos)) * 64 + d;
                    if (sec == 0)      *reinterpret_cast<__half2*>(&g_q[dst]) = hv;
                    else if (sec == 1) *reinterpret_cast<__half2*>(&g_k[dst]) = hv;
                    else               *reinterpret_cast<__half2*>(&g_v[dst]) = hv;
                }
            }
        }
    }
}

// ---------------------------------------------------------------------------
// Attention: one warp per (b*s, head). mma.sync, register softmax.
// ---------------------------------------------------------------------------
__global__ __launch_bounds__(64) void attn_kernel(const float* __restrict__ pos_bias)
{
    __shared__ __half sh[2][7168];
    const int lane = threadIdx.x & 31, w = threadIdx.x >> 5;
    const int hh = blockIdx.x * 2 + w;
    const int bs = hh >> 3, h = hh & 7, b = bs >> 10;
    const int g = lane >> 2, c2 = (lane & 3) * 2;

    const __half* qg = g_q + (size_t)hh * 2048;
    const __half* kg = g_k + (size_t)hh * 2048;
    const __half* vg = g_v + (size_t)hh * 2048;
    __half* Qs = sh[w];
    __half* Ks = sh[w] + 2304;
    __half* Vt = sh[w] + 4608;

    if (g_mask[b]) {
#pragma unroll
        for (int it = 0; it < 16; it++) {
            int i = it * 32 + lane;
            int tok = i >> 4, p4 = (i & 15) * 4;
            uint2 v = *reinterpret_cast<const uint2*>(&vg[tok * 64 + p4]);
            *reinterpret_cast<uint2*>(
                &g_att[((size_t)(bs * 32 + tok)) * 512 + h * 64 + p4]) = v;
        }
        return;
    }

#pragma unroll
    for (int it = 0; it < 16; it++) {
        int i = it * 32 + lane;
        int tok = i >> 4, p4 = (i & 15) * 4;
        uint2 qv = *reinterpret_cast<const uint2*>(&qg[tok * 64 + p4]);
        *reinterpret_cast<uint2*>(&Qs[tok * 72 + p4]) = qv;
        uint2 kv = *reinterpret_cast<const uint2*>(&kg[tok * 64 + p4]);
        *reinterpret_cast<uint2*>(&Ks[tok * 72 + p4]) = kv;
        uint2 vv = *reinterpret_cast<const uint2*>(&vg[tok * 64 + p4]);
        __half hbuf[4];
        *reinterpret_cast<uint2*>(hbuf) = vv;
#pragma unroll
        for (int q = 0; q < 4; q++) Vt[(p4 + q) * 40 + tok] = hbuf[q];
    }
    __syncwarp();

    float sacc[2][4][4];
#pragma unroll
    for (int a = 0; a < 2; a++)
#pragma unroll
        for (int n = 0; n < 4; n++)
#pragma unroll
            for (int e = 0; e < 4; e++) sacc[a][n][e] = 0.f;

#pragma unroll
    for (int kt = 0; kt < 4; kt++) {
        const int k0 = kt * 16;
        unsigned aq[2][4];
#pragma unroll
        for (int mt = 0; mt < 2; mt++) {
            int m0 = mt * 16;
            aq[mt][0] = *reinterpret_cast<unsigned*>(&Qs[(m0 + g) * 72 + k0 + c2]);
            aq[mt][1] = *reinterpret_cast<unsigned*>(&Qs[(m0 + g + 8) * 72 + k0 + c2]);
            aq[mt][2] = *reinterpret_cast<unsigned*>(&Qs[(m0 + g) * 72 + k0 + c2 + 8]);
            aq[mt][3] = *reinterpret_cast<unsigned*>(&Qs[(m0 + g + 8) * 72 + k0 + c2 + 8]);
        }
        unsigned bk[4][2];
#pragma unroll
        for (int nt = 0; nt < 4; nt++) {
            int n = nt * 8 + g;
            bk[nt][0] = *reinterpret_cast<unsigned*>(&Ks[n * 72 + k0 + c2]);
            bk[nt][1] = *reinterpret_cast<unsigned*>(&Ks[n * 72 + k0 + c2 + 8]);
        }
#pragma unroll
        for (int mt = 0; mt < 2; mt++)
#pragma unroll
            for (int nt = 0; nt < 4; nt++)
                MMA_16816(sacc[mt][nt], aq[mt], bk[nt][0], bk[nt][1]);
    }

    const float* pb = pos_bias + h * 1024;
#pragma unroll
    for (int mt = 0; mt < 2; mt++)
#pragma unroll
        for (int nt = 0; nt < 4; nt++)
#pragma unroll
            for (int hf = 0; hf < 2; hf++) {
                int r = mt * 16 + g + hf * 8;
                int col = nt * 8 + c2;
                sacc[mt][nt][hf * 2 + 0] += pb[r * 32 + col];
                sacc[mt][nt][hf * 2 + 1] += pb[r * 32 + col + 1];
            }

#pragma unroll
    for (int mt = 0; mt < 2; mt++)
#pragma unroll
        for (int hf = 0; hf < 2; hf++) {
            float mx = -1e30f;
#pragma unroll
            for (int nt = 0; nt < 4; nt++) {
                mx = fmaxf(mx, sacc[mt][nt][hf * 2 + 0]);
                mx = fmaxf(mx, sacc[mt][nt][hf * 2 + 1]);
            }
            mx = fmaxf(mx, __shfl_xor_sync(0xffffffffu, mx, 1));
            mx = fmaxf(mx, __shfl_xor_sync(0xffffffffu, mx, 2));
            float sum = 0.f;
#pragma unroll
            for (int nt = 0; nt < 4; nt++) {
#pragma unroll
                for (int j = 0; j < 2; j++) {
                    float e = __expf(sacc[mt][nt][hf * 2 + j] - mx);
                    sacc[mt][nt][hf * 2 + j] = e;
                    sum += e;
                }
            }
            sum += __shfl_xor_sync(0xffffffffu, sum, 1);
            sum += __shfl_xor_sync(0xffffffffu, sum, 2);
            float inv = 1.f / sum;
#pragma unroll
            for (int nt = 0; nt < 4; nt++) {
                sacc[mt][nt][hf * 2 + 0] *= inv;
                sacc[mt][nt][hf * 2 + 1] *= inv;
            }
        }

    unsigned pa[2][2][4];
#pragma unroll
    for (int mt = 0; mt < 2; mt++)
#pragma unroll
        for (int kt = 0; kt < 2; kt++) {
            pa[mt][kt][0] = pack_h2(sacc[mt][2 * kt][0], sacc[mt][2 * kt][1]);
            pa[mt][kt][1] = pack_h2(sacc[mt][2 * kt][2], sacc[mt][2 * kt][3]);
            pa[mt][kt][2] = pack_h2(sacc[mt][2 * kt + 1][0], sacc[mt][2 * kt + 1][1]);
            pa[mt][kt][3] = pack_h2(sacc[mt][2 * kt + 1][2], sacc[mt][2 * kt + 1][3]);
        }

    float oacc[2][8][4];
#pragma unroll
    for (int a = 0; a < 2; a++)
#pragma unroll
        for (int d = 0; d < 8; d++)
#pragma unroll
            for (int e = 0; e < 4; e++) oacc[a][d][e] = 0.f;

#pragma unroll
    for (int dt = 0; dt < 8; dt++) {
        unsigned bv[2][2];
#pragma unroll
        for (int kt = 0; kt < 2; kt++) {
            bv[kt][0] = *reinterpret_cast<unsigned*>(&Vt[(dt * 8 + g) * 40 + kt * 16 + c2]);
            bv[kt][1] = *reinterpret_cast<unsigned*>(&Vt[(dt * 8 + g) * 40 + kt * 16 + c2 + 8]);
        }
#pragma unroll
        for (int mt = 0; mt < 2; mt++)
#pragma unroll
            for (int kt = 0; kt < 2; kt++)
                MMA_16816(oacc[mt][dt], pa[mt][kt], bv[kt][0], bv[kt][1]);
    }

#pragma unroll
    for (int mt = 0; mt < 2; mt++)
#pragma unroll
        for (int dt = 0; dt < 8; dt++)
#pragma unroll
            for (int hf = 0; hf < 2; hf++) {
                int r = mt * 16 + g + hf * 8;
                int d = dt * 8 + c2;
                __half2 hv = __floats2half2_rn(oacc[mt][dt][hf * 2 + 0],
                                               oacc[mt][dt][hf * 2 + 1]);
                *reinterpret_cast<__half2*>(
                    &g_att[((size_t)(bs * 32 + r)) * 512 + h * 64 + d]) = hv;
            }
}

// ---------------------------------------------------------------------------
extern "C" void kernel_launch(void* const* d_in, const int* in_sizes, int n_in,
                              void* d_out, int out_size)
{
    const float *x = 0, *pos_bias = 0, *wq = 0, *wkv = 0, *wout = 0, *invf = 0;
    const unsigned char* maskp = 0;
    for (int i = 0; i < n_in; i++) {
        int s = in_sizes[i];
        if (s == 33554432)      x = (const float*)d_in[i];
        else if (s == 8192)     pos_bias = (const float*)d_in[i];
        else if (s == 2)        maskp = (const unsigned char*)d_in[i];
        else if (s == 524288)   wkv = (const float*)d_in[i];
        else if (s == 32)       invf = (const float*)d_in[i];
        else if (s == 262144) { if (!wq) wq = (const float*)d_in[i];
                                else     wout = (const float*)d_in[i]; }
    }
    float* out = (float*)d_out;

    const int SMEM = 3 * 32768;
    cudaFuncSetAttribute(hgemm<0>, cudaFuncAttributeMaxDynamicSharedMemorySize, SMEM);
    cudaFuncSetAttribute(hgemm<1>, cudaFuncAttributeMaxDynamicSharedMemorySize, SMEM);

    prep_kernel<<<2048, 256>>>(wq, wkv, wout, invf, maskp, x);
    hgemm<0><<<dim3(12, 512), 128, SMEM>>>(nullptr);   // QKV + RoPE
    attn_kernel<<<8192, 64>>>(pos_bias);               // per-head attention
    hgemm<1><<<dim3(4, 512), 128, SMEM>>>(out);        // out projection
}

// round 14
// speedup vs baseline: 2.1634x; 1.4587x over previous
#include <cuda_runtime.h>
#include <cuda_fp16.h>
#include <cstdint>

// ---------------------------------------------------------------------------
//   x: (2,1024,32,512) fp32 -> M=65536, K=512
//   qkv = x @ [w_q|w_kv] -> N=1536 ; attention per (b,s,h): n=32, d=64
//   out = att @ w_out -> (65536, 512) fp32
// ---------------------------------------------------------------------------

#define NELEM_QKV 33554432

__device__ __half g_xh[(size_t)65536 * 512];   // x converted to fp16
__device__ __half g_wqkvT[1536 * 512];         // [n][k] K-major
__device__ __half g_woutT[512 * 512];          // [n][k] K-major
__device__ __half g_q[NELEM_QKV];
__device__ __half g_k[NELEM_QKV];
__device__ __half g_v[NELEM_QKV];
__device__ __half g_att[(size_t)65536 * 512];
__device__ float  g_cos[1024];                 // [pos][freq]
__device__ float  g_sin[1024];
__device__ int    g_mask[2];

__device__ __forceinline__ unsigned pack_h2(float a, float b) {
    __half2 h = __floats2half2_rn(a, b);
    return *reinterpret_cast<unsigned*>(&h);
}
__device__ __forceinline__ uint32_t smem_u32(const void* p) {
    uint32_t r;
    asm("{ .reg .u64 t; cvta.to.shared.u64 t, %1; cvt.u32.u64 %0, t; }"
        : "=r"(r) : "l"(p));
    return r;
}
__device__ __forceinline__ void cp16(uint32_t d, const void* s) {
    asm volatile("cp.async.cg.shared.global [%0], [%1], 16;" :: "r"(d), "l"(s) : "memory");
}
#define CP_COMMIT() asm volatile("cp.async.commit_group;" ::: "memory")

#define MMA_16816(D, A, B0, B1)                                               \
    asm volatile(                                                             \
        "mma.sync.aligned.m16n8k16.row.col.f32.f16.f16.f32 "                  \
        "{%0,%1,%2,%3},{%4,%5,%6,%7},{%8,%9},{%0,%1,%2,%3};"                  \
        : "+f"(D[0]), "+f"(D[1]), "+f"(D[2]), "+f"(D[3])                      \
        : "r"(A[0]), "r"(A[1]), "r"(A[2]), "r"(A[3]), "r"(B0), "r"(B1))

#define LDSM4(R, addr)                                                        \
    asm volatile("ldmatrix.sync.aligned.m8n8.x4.shared.b16 {%0,%1,%2,%3}, [%4];" \
        : "=r"((R)[0]), "=r"((R)[1]), "=r"((R)[2]), "=r"((R)[3]) : "r"(addr))

#define LDSM4T(R, addr)                                                       \
    asm volatile("ldmatrix.sync.aligned.m8n8.x4.trans.shared.b16 {%0,%1,%2,%3}, [%4];" \
        : "=r"((R)[0]), "=r"((R)[1]), "=r"((R)[2]), "=r"((R)[3]) : "r"(addr))

// ---------------------------------------------------------------------------
// Prep: x -> fp16, weights transposed to [n][k] fp16, rope tables, mask.
// ---------------------------------------------------------------------------
__global__ void prep_kernel(const float* __restrict__ wq,
                            const float* __restrict__ wkv,
                            const float* __restrict__ wout,
                            const float* __restrict__ invf,
                            const unsigned char* __restrict__ maskp,
                            const float* __restrict__ x)
{
    int i = blockIdx.x * blockDim.x + threadIdx.x;
    int stride = gridDim.x * blockDim.x;

    for (size_t idx = i; idx < (size_t)65536 * 512 / 4; idx += stride) {
        float4 v = reinterpret_cast<const float4*>(x)[idx];
        uint2 st;
        st.x = pack_h2(v.x, v.y);
        st.y = pack_h2(v.z, v.w);
        *reinterpret_cast<uint2*>(&g_xh[idx * 4]) = st;
    }
    for (int idx = i; idx < 1536 * 512; idx += stride) {
        int n = idx >> 9, k = idx & 511;
        float v = (n < 512) ? wq[k * 512 + n] : wkv[k * 1024 + (n - 512)];
        g_wqkvT[idx] = __float2half_rn(v);
    }
    for (int idx = i; idx < 512 * 512; idx += stride) {
        int n = idx >> 9, k = idx & 511;
        g_woutT[idx] = __float2half_rn(wout[k * 512 + n]);
    }
    for (int idx = i; idx < 1024; idx += stride) {
        int pos = idx >> 5, f = idx & 31;
        float a = (float)pos * invf[f];
        g_cos[idx] = cosf(a);
        g_sin[idx] = sinf(a);
    }
    if (i == 0) {
        unsigned char c0 = maskp[0], c1 = maskp[1], c2 = maskp[2], c3 = maskp[3];
        int m0, m1;
        if (c1 | c2 | c3) { m0 = (c0 != 0); m1 = (c1 != 0); }
        else {
            int i1 = ((const int*)maskp)[1];
            if (i1 == 0 || i1 == 1) { m0 = (c0 != 0); m1 = i1; }
            else                    { m0 = (c0 != 0); m1 = (c1 != 0); }
        }
        g_mask[0] = m0; g_mask[1] = m1;
    }
}

// ---------------------------------------------------------------------------
// HGEMM (round-5 proven config): C(128x128) = A[m][k]*B[n][k]^T, fp16/fp32.
// 8 warps (4xM, 2xN), warp tile 32x64, BK=64, 3-stage cp.async ring,
// 128B-XOR swizzled smem, ldmatrix.x4 fragments.
// MODE 0: A=g_xh, B=g_wqkvT -> RoPE/scale epilogue, scatter q/k/v.
//         Mask-aware: masked batches skip q/k CTAs entirely; v also lands in
//         g_att (attn == identity there, so out == v).
// MODE 1: A=g_att, B=g_woutT -> fp32 store to d_out.
// ---------------------------------------------------------------------------
template <int MODE>
__global__ __launch_bounds__(256, 2) void hgemm(float* __restrict__ Cout)
{
    const __half* __restrict__ AG = (MODE == 0) ? g_xh : g_att;
    const __half* __restrict__ BG = (MODE == 0) ? g_wqkvT : g_woutT;

    const int bm0 = blockIdx.y * 128, bn0 = blockIdx.x * 128;

    int mskB = 0;
    if (MODE == 0) {
        mskB = g_mask[bm0 >> 15];            // batch of this row-block
        if (mskB && bn0 < 1024) return;      // q,k never used for masked batch
    }

    extern __shared__ char smem[];                 // 3 * 32768
    const uint32_t sbase = smem_u32(smem);

    const int tid = threadIdx.x, lane = tid & 31, warp = tid >> 5;
    const int warpM = warp & 3, warpN = warp >> 2;
    const int g = lane >> 2, c2 = (lane & 3) * 2;

    const int lr = tid >> 3, lc = tid & 7;         // 32 rows/pass, 8 chunks/row
    auto load_stage = [&](int kb, uint32_t buf) {
#pragma unroll
        for (int j = 0; j < 4; j++) {
            int r = lr + j * 32;
            uint32_t d = buf + r * 128 + ((lc * 16) ^ ((r & 7) << 4));
            cp16(d, AG + (size_t)(bm0 + r) * 512 + kb + lc * 8);
            cp16(d + 16384, BG + (size_t)(bn0 + r) * 512 + kb + lc * 8);
        }
    };

    float acc[2][8][4];
#pragma unroll
    for (int a = 0; a < 2; a++)
#pragma unroll
        for (int b = 0; b < 8; b++)
#pragma unroll
            for (int c = 0; c < 4; c++) acc[a][b][c] = 0.f;

    load_stage(0, sbase);            CP_COMMIT();
    load_stage(64, sbase + 32768);   CP_COMMIT();
    load_stage(128, sbase + 65536);  CP_COMMIT();

    const uint32_t sel = (lane & 7) << 4;
    const uint32_t klane = (lane >> 4) * 16;                       // bytes
    const uint32_t arow = (uint32_t)(warpM * 32 + (lane & 15)) * 128;
    const uint32_t brow = (uint32_t)(warpN * 64 + (lane & 15)) * 128;

    for (int ks = 0; ks < 8; ks++) {
        asm volatile("cp.async.wait_group 2;" ::: "memory");
        __syncthreads();
        const uint32_t bufA = sbase + (ks % 3) * 32768;
        const uint32_t bufB = bufA + 16384;

#pragma unroll
        for (int kk = 0; kk < 4; kk++) {
            const uint32_t kc = (klane + kk * 32) ^ sel;
            unsigned afr[2][4];
#pragma unroll
            for (int mt = 0; mt < 2; mt++)
                LDSM4(afr[mt], bufA + arow + mt * 2048 + kc);
            unsigned braw[4][4];
#pragma unroll
            for (int nt2 = 0; nt2 < 4; nt2++)
                LDSM4(braw[nt2], bufB + brow + nt2 * 2048 + kc);
#pragma unroll
            for (int mt = 0; mt < 2; mt++)
#pragma unroll
                for (int nt2 = 0; nt2 < 4; nt2++) {
                    MMA_16816(acc[mt][2 * nt2 + 0], afr[mt], braw[nt2][0], braw[nt2][2]);
                    MMA_16816(acc[mt][2 * nt2 + 1], afr[mt], braw[nt2][1], braw[nt2][3]);
                }
        }
        __syncthreads();
        if (ks + 3 < 8) load_stage((ks + 3) * 64, sbase + (ks % 3) * 32768);
        CP_COMMIT();                      // empty group when nothing loaded
    }

    // ---- epilogue ----
#pragma unroll
    for (int mt = 0; mt < 2; mt++) {
#pragma unroll
        for (int nt = 0; nt < 8; nt++) {
            const int col = bn0 + warpN * 64 + nt * 8 + c2;
#pragma unroll
            for (int hf = 0; hf < 2; hf++) {
                const int r = bm0 + warpM * 32 + mt * 16 + g + hf * 8;
                float v0 = acc[mt][nt][hf * 2 + 0];
                float v1 = acc[mt][nt][hf * 2 + 1];
                if (MODE == 1) {
                    float2 st; st.x = v0; st.y = v1;
                    *reinterpret_cast<float2*>(&Cout[(size_t)r * 512 + col]) = st;
                } else {
                    const int sec = col >> 9;       // 0=q, 1=k, 2=v
                    const int jh = col & 511;
                    const int h = jh >> 6, d = jh & 63, f = d >> 1;
                    const int pos = r & 31, bs = r >> 5;
                    if (sec == 0) { v0 *= 0.125f; v1 *= 0.125f; }
                    if (sec < 2) {
                        float cs = g_cos[pos * 32 + f], sn = g_sin[pos * 32 + f];
                        float o0 = v0 * cs - v1 * sn;
                        float o1 = v1 * cs + v0 * sn;
                        v0 = o0; v1 = o1;
                    }
                    __half2 hv = __floats2half2_rn(v0, v1);
                    size_t dst = ((size_t)((bs * 8 + h) * 32 + pos)) * 64 + d;
                    if (sec == 0)      *reinterpret_cast<__half2*>(&g_q[dst]) = hv;
                    else if (sec == 1) *reinterpret_cast<__half2*>(&g_k[dst]) = hv;
                    else {
                        *reinterpret_cast<__half2*>(&g_v[dst]) = hv;
                        if (mskB)   // identity attention: out row == v row
                            *reinterpret_cast<__half2*>(&g_att[(size_t)r * 512 + jh]) = hv;
                    }
                }
            }
        }
    }
}

// ---------------------------------------------------------------------------
// Attention v2: one warp per (b*s, head), 4 warps/block.
// Q/K fragments via ldmatrix.x4; V fragments via ldmatrix.x4.trans
// (no scalar transpose). Masked batches handled by hgemm<0> -> early return.
// smem/warp: Q,K,V each [32][72] halves (row stride 144B, LDSM conflict-free).
// ---------------------------------------------------------------------------
__global__ __launch_bounds__(128) void attn_kernel(const float* __restrict__ pos_bias)
{
    extern __shared__ __half ash[];                // 4 * 3 * 2304 halves
    const int lane = threadIdx.x & 31, w = threadIdx.x >> 5;
    const int hh = blockIdx.x * 4 + w;             // (b*s)*8 + h
    const int bs = hh >> 3, h = hh & 7, b = bs >> 10;
    const int g = lane >> 2, c2 = (lane & 3) * 2;

    if (g_mask[b]) return;                         // out == v, written by hgemm<0>

    __half* Qs = ash + w * 6912;
    __half* Ks = Qs + 2304;
    __half* Vs = Ks + 2304;
    const __half* qg = g_q + (size_t)hh * 2048;
    const __half* kg = g_k + (size_t)hh * 2048;
    const __half* vg = g_v + (size_t)hh * 2048;

#pragma unroll
    for (int it = 0; it < 8; it++) {
        int idx = it * 32 + lane;                  // 256 uint4 per tensor
        int row = idx >> 3, c8 = (idx & 7) * 8;
        *reinterpret_cast<uint4*>(&Qs[row * 72 + c8]) =
            *reinterpret_cast<const uint4*>(&qg[row * 64 + c8]);
        *reinterpret_cast<uint4*>(&Ks[row * 72 + c8]) =
            *reinterpret_cast<const uint4*>(&kg[row * 64 + c8]);
        *reinterpret_cast<uint4*>(&Vs[row * 72 + c8]) =
            *reinterpret_cast<const uint4*>(&vg[row * 64 + c8]);
    }
    __syncwarp();

    const uint32_t qb = smem_u32(Qs), kb = smem_u32(Ks), vb = smem_u32(Vs);
    const uint32_t rsel = (uint32_t)(lane & 15) * 144;
    const uint32_t koff = (uint32_t)(lane >> 4) * 16;   // bytes

    // S = Q K^T  (32x32, fp32 accum)
    float sacc[2][4][4];
#pragma unroll
    for (int a = 0; a < 2; a++)
#pragma unroll
        for (int n = 0; n < 4; n++)
#pragma unroll
            for (int e = 0; e < 4; e++) sacc[a][n][e] = 0.f;

#pragma unroll
    for (int kt = 0; kt < 4; kt++) {
        const uint32_t kc = kt * 32 + koff;
        unsigned aq[2][4];
#pragma unroll
        for (int mt = 0; mt < 2; mt++)
            LDSM4(aq[mt], qb + mt * 16 * 144 + rsel + kc);
        unsigned bkr[2][4];
#pragma unroll
        for (int ng = 0; ng < 2; ng++)
            LDSM4(bkr[ng], kb + ng * 16 * 144 + rsel + kc);
#pragma unroll
        for (int mt = 0; mt < 2; mt++)
#pragma unroll
            for (int nt = 0; nt < 4; nt++)
                MMA_16816(sacc[mt][nt], aq[mt],
                          bkr[nt >> 1][nt & 1], bkr[nt >> 1][(nt & 1) + 2]);
    }

    // + pos_bias
    const float* pb = pos_bias + h * 1024;
#pragma unroll
    for (int mt = 0; mt < 2; mt++)
#pragma unroll
        for (int nt = 0; nt < 4; nt++)
#pragma unroll
            for (int hf = 0; hf < 2; hf++) {
                int r = mt * 16 + g + hf * 8;
                int col = nt * 8 + c2;
                sacc[mt][nt][hf * 2 + 0] += pb[r * 32 + col];
                sacc[mt][nt][hf * 2 + 1] += pb[r * 32 + col + 1];
            }

    // Row softmax (butterfly over 4 lanes sharing each row)
#pragma unroll
    for (int mt = 0; mt < 2; mt++)
#pragma unroll
        for (int hf = 0; hf < 2; hf++) {
            float mx = -1e30f;
#pragma unroll
            for (int nt = 0; nt < 4; nt++) {
                mx = fmaxf(mx, sacc[mt][nt][hf * 2 + 0]);
                mx = fmaxf(mx, sacc[mt][nt][hf * 2 + 1]);
            }
            mx = fmaxf(mx, __shfl_xor_sync(0xffffffffu, mx, 1));
            mx = fmaxf(mx, __shfl_xor_sync(0xffffffffu, mx, 2));
            float sum = 0.f;
#pragma unroll
            for (int nt = 0; nt < 4; nt++) {
#pragma unroll
                for (int j = 0; j < 2; j++) {
                    float e = __expf(sacc[mt][nt][hf * 2 + j] - mx);
                    sacc[mt][nt][hf * 2 + j] = e;
                    sum += e;
                }
            }
            sum += __shfl_xor_sync(0xffffffffu, sum, 1);
            sum += __shfl_xor_sync(0xffffffffu, sum, 2);
            float inv = 1.f / sum;
#pragma unroll
            for (int nt = 0; nt < 4; nt++) {
                sacc[mt][nt][hf * 2 + 0] *= inv;
                sacc[mt][nt][hf * 2 + 1] *= inv;
            }
        }

    // P (C-layout) -> A-fragments
    unsigned pa[2][2][4];
#pragma unroll
    for (int mt = 0; mt < 2; mt++)
#pragma unroll
        for (int kt = 0; kt < 2; kt++) {
            pa[mt][kt][0] = pack_h2(sacc[mt][2 * kt][0], sacc[mt][2 * kt][1]);
            pa[mt][kt][1] = pack_h2(sacc[mt][2 * kt][2], sacc[mt][2 * kt][3]);
            pa[mt][kt][2] = pack_h2(sacc[mt][2 * kt + 1][0], sacc[mt][2 * kt + 1][1]);
            pa[mt][kt][3] = pack_h2(sacc[mt][2 * kt + 1][2], sacc[mt][2 * kt + 1][3]);
        }

    // O = P V ; V B-fragments via ldmatrix.trans on row-major V[tok][d]
    float oacc[2][8][4];
#pragma unroll
    for (int a = 0; a < 2; a++)
#pragma unroll
        for (int d = 0; d < 8; d++)
#pragma unroll
            for (int e = 0; e < 4; e++) oacc[a][d][e] = 0.f;

#pragma unroll
    for (int dt2 = 0; dt2 < 4; dt2++) {            // 16 d-cols per iter
        unsigned bv[2][4];
#pragma unroll
        for (int kt = 0; kt < 2; kt++) {
            uint32_t addr = vb + (uint32_t)(kt * 16 + ((lane >> 3) & 1) * 8 + (lane & 7)) * 144
                               + dt2 * 32 + (lane >> 4) * 16;
            LDSM4T(bv[kt], addr);
        }
#pragma unroll
        for (int mt = 0; mt < 2; mt++)
#pragma unroll
            for (int kt = 0; kt < 2; kt++) {
                MMA_16816(oacc[mt][2 * dt2 + 0], pa[mt][kt], bv[kt][0], bv[kt][1]);
                MMA_16816(oacc[mt][2 * dt2 + 1], pa[mt][kt], bv[kt][2], bv[kt][3]);
            }
    }

    // Write O rows of the (b,s,tok, h*64+d) matrix for the out GEMM.
#pragma unroll
    for (int mt = 0; mt < 2; mt++)
#pragma unroll
        for (int dt = 0; dt < 8; dt++)
#pragma unroll
            for (int hf = 0; hf < 2; hf++) {
                int r = mt * 16 + g + hf * 8;
                int d = dt * 8 + c2;
                __half2 hv = __floats2half2_rn(oacc[mt][dt][hf * 2 + 0],
                                               oacc[mt][dt][hf * 2 + 1]);
                *reinterpret_cast<__half2*>(
                    &g_att[((size_t)(bs * 32 + r)) * 512 + h * 64 + d]) = hv;
            }
}

// ---------------------------------------------------------------------------
extern "C" void kernel_launch(void* const* d_in, const int* in_sizes, int n_in,
                              void* d_out, int out_size)
{
    const float *x = 0, *pos_bias = 0, *wq = 0, *wkv = 0, *wout = 0, *invf = 0;
    const unsigned char* maskp = 0;
    for (int i = 0; i < n_in; i++) {
        int s = in_sizes[i];
        if (s == 33554432)      x = (const float*)d_in[i];
        else if (s == 8192)     pos_bias = (const float*)d_in[i];
        else if (s == 2)        maskp = (const unsigned char*)d_in[i];
        else if (s == 524288)   wkv = (const float*)d_in[i];
        else if (s == 32)       invf = (const float*)d_in[i];
        else if (s == 262144) { if (!wq) wq = (const float*)d_in[i];
                                else     wout = (const float*)d_in[i]; }
    }
    float* out = (float*)d_out;

    const int SMEM = 3 * 32768;
    const int ATTN_SMEM = 4 * 3 * 2304 * 2;        // 55296 B
    cudaFuncSetAttribute(hgemm<0>, cudaFuncAttributeMaxDynamicSharedMemorySize, SMEM);
    cudaFuncSetAttribute(hgemm<1>, cudaFuncAttributeMaxDynamicSharedMemorySize, SMEM);
    cudaFuncSetAttribute(attn_kernel, cudaFuncAttributeMaxDynamicSharedMemorySize, ATTN_SMEM);

    prep_kernel<<<2048, 256>>>(wq, wkv, wout, invf, maskp, x);
    hgemm<0><<<dim3(12, 512), 256, SMEM>>>(nullptr);       // QKV + RoPE (mask-aware)
    attn_kernel<<<4096, 128, ATTN_SMEM>>>(pos_bias);       // per-head attention
    hgemm<1><<<dim3(4, 512), 256, SMEM>>>(out);            // out projection
}